// round 17
// baseline (speedup 1.0000x reference)
#include <cuda_runtime.h>
#include <math.h>
#include <float.h>
#include <stdint.h>

// Problem constants
#define Bv   8
#define Lv   4096
#define LP   4097          // L + 1 (bias token)
#define KDv  512
#define EDv  1024
#define DK   64            // KD / H
#define DV   128           // ED / H
#define BH   64            // B * H
#define KCHUNK   (LP * DK)
#define VCHUNK   (LP * DV)
#define KBATCH   (Lv * KDv)
#define VBATCH   (Lv * EDv)
#define NT   8             // j-tiles -> 512 blocks = single wave
#define TILE 513           // ceil(4097 / 8)
#define BLKS_PER_BATCH (NT * 8)   // 64

// Scratch
__device__ float g_bsum[BH * NT];
__device__ float g_partial[BH * NT * DV];
__device__ int   g_cnt[Bv];        // zero-init; self-resetting

// ---------------------------------------------------------------------------
// Fused kernel (R15/16 body) + last-block-per-batch LayerNorm epilogue.
// ---------------------------------------------------------------------------
__global__ void __launch_bounds__(256) k_fused(
        const float* __restrict__ keys,
        const float* __restrict__ k_bias,
        const float* __restrict__ values,
        const float* __restrict__ v_bias,
        const float* __restrict__ query,
        const float* __restrict__ sw,
        const float* __restrict__ sb,
        const float* __restrict__ gamma,
        const float* __restrict__ beta,
        float* __restrict__ out) {
    __shared__ float4 sq[16];
    __shared__ float4 red[8][32];
    __shared__ float  shs[8];

    int tile = blockIdx.x;
    int bh   = blockIdx.y;
    int b = bh >> 3, h = bh & 7;
    int t    = threadIdx.x;
    int w    = t >> 5;
    int lane = t & 31;
    int half = lane >> 4;
    int li   = lane & 15;
    int c    = lane;

    if (t < 16) sq[t] = *((const float4*)(query + h * DK) + t);
    __syncthreads();

    const float* swh = sw + h * LP;
    const float* sbh = sb + h * LP;
    int kchunk = h * KCHUNK;
    int vchunk = h * VCHUNK;
    const float* kbat = keys   + (size_t)b * KBATCH;
    const float* vbat = values + (size_t)b * VBATCH;

    int j0 = tile * TILE;
    int j1 = min(j0 + TILE, LP);

    float4 acc  = make_float4(0.f, 0.f, 0.f, 0.f);
    float  esum = 0.0f;
    float4 qv   = sq[li];

    int j = j0 + w;
    // main loop: 4 rows (j, j+8, j+16, j+24) per iteration
    for (; j + 24 < j1; j += 32) {
        int jkA = j + half * 8;
        int jkB = j + 16 + half * 8;
        int fkA = kchunk + jkA * DK + li * 4;
        int fkB = kchunk + jkB * DK + li * 4;
        const float* kpA = (fkA >= KBATCH) ? (k_bias + (fkA - KBATCH)) : (kbat + fkA);
        const float* kpB = (fkB >= KBATCH) ? (k_bias + (fkB - KBATCH)) : (kbat + fkB);
        float4 kvA = __ldcs((const float4*)kpA);
        float4 kvB = __ldcs((const float4*)kpB);

        int f0 = vchunk + j * DV;
        int f1 = f0 + 8 * DV, f2 = f0 + 16 * DV, f3 = f0 + 24 * DV;
        const float* r0 = (f0 >= VBATCH) ? (v_bias + (f0 - VBATCH)) : (vbat + f0);
        const float* r1 = (f1 >= VBATCH) ? (v_bias + (f1 - VBATCH)) : (vbat + f1);
        const float* r2 = (f2 >= VBATCH) ? (v_bias + (f2 - VBATCH)) : (vbat + f2);
        const float* r3 = (f3 >= VBATCH) ? (v_bias + (f3 - VBATCH)) : (vbat + f3);
        float4 v0 = __ldcs((const float4*)(r0 + c * 4));
        float4 v1 = __ldcs((const float4*)(r1 + c * 4));
        float4 v2 = __ldcs((const float4*)(r2 + c * 4));
        float4 v3 = __ldcs((const float4*)(r3 + c * 4));

        float sA = kvA.x * qv.x + kvA.y * qv.y + kvA.z * qv.z + kvA.w * qv.w;
        float sB = kvB.x * qv.x + kvB.y * qv.y + kvB.z * qv.z + kvB.w * qv.w;
        #pragma unroll
        for (int o = 8; o > 0; o >>= 1) {
            sA += __shfl_xor_sync(0xffffffffu, sA, o);
            sB += __shfl_xor_sync(0xffffffffu, sB, o);
        }
        float eA2 = expf(sA * __ldg(swh + jkA) + __ldg(sbh + jkA));
        float eB2 = expf(sB * __ldg(swh + jkB) + __ldg(sbh + jkB));
        float e0 = __shfl_sync(0xffffffffu, eA2, 0);
        float e1 = __shfl_sync(0xffffffffu, eA2, 16);
        float e2 = __shfl_sync(0xffffffffu, eB2, 0);
        float e3 = __shfl_sync(0xffffffffu, eB2, 16);

        acc.x += e0 * v0.x + e1 * v1.x + e2 * v2.x + e3 * v3.x;
        acc.y += e0 * v0.y + e1 * v1.y + e2 * v2.y + e3 * v3.y;
        acc.z += e0 * v0.z + e1 * v1.z + e2 * v2.z + e3 * v3.z;
        acc.w += e0 * v0.w + e1 * v1.w + e2 * v2.w + e3 * v3.w;
        if (lane == 0) esum += (e0 + e1) + (e2 + e3);
    }
    // tail: single rows
    for (; j < j1; j += 8) {
        int fk = kchunk + j * DK + li * 4;
        const float* kp = (fk >= KBATCH) ? (k_bias + (fk - KBATCH)) : (kbat + fk);
        float4 kv = __ldcs((const float4*)kp);
        float s = kv.x * qv.x + kv.y * qv.y + kv.z * qv.z + kv.w * qv.w;
        #pragma unroll
        for (int o = 8; o > 0; o >>= 1)
            s += __shfl_xor_sync(0xffffffffu, s, o);
        float e = expf(s * __ldg(swh + j) + __ldg(sbh + j));
        e = __shfl_sync(0xffffffffu, e, 0);

        int fA = vchunk + j * DV;
        const float* rA = (fA >= VBATCH) ? (v_bias + (fA - VBATCH)) : (vbat + fA);
        float4 vA = __ldcs((const float4*)(rA + c * 4));
        acc.x += e * vA.x;
        acc.y += e * vA.y;
        acc.z += e * vA.z;
        acc.w += e * vA.w;
        if (lane == 0) esum += e;
    }

    // cross-warp reduce, write partials
    red[w][c] = acc;
    if (lane == 0) shs[w] = esum;
    __syncthreads();
    if (w == 0) {
        float4 a = red[0][c];
        #pragma unroll
        for (int ww = 1; ww < 8; ww++) {
            float4 x = red[ww][c];
            a.x += x.x; a.y += x.y; a.z += x.z; a.w += x.w;
        }
        *(float4*)(g_partial + (bh * NT + tile) * DV + c * 4) = a;
        if (lane == 0) {
            float s = 0.0f;
            #pragma unroll
            for (int ww = 0; ww < 8; ww++) s += shs[ww];
            g_bsum[bh * NT + tile] = s;
        }
    }

    // ---- last-block-per-batch LayerNorm epilogue ----
    __threadfence();
    __syncthreads();
    __shared__ int lastFlag;
    if (t == 0)
        lastFlag = (atomicAdd(&g_cnt[b], 1) == BLKS_PER_BATCH - 1);
    __syncthreads();
    if (!lastFlag) return;
    __threadfence();

    __shared__ float sh_invS[8];
    __shared__ float sh_s[8];
    __shared__ float sh_q[8];

    // Phase A: per-head Sexp (warp wp -> head wp; NT=8 values)
    {
        const float* bs = g_bsum + (b * 8 + w) * NT;
        float s = (lane < NT) ? __ldcg(bs + lane) : 0.0f;
        #pragma unroll
        for (int o = 16; o > 0; o >>= 1)
            s += __shfl_xor_sync(0xffffffffu, s, o);
        if (lane == 0) sh_invS[w] = 1.0f / s;
    }
    __syncthreads();

    // Phase B: reduce partials, normalize, LayerNorm (thread t -> 4 dims)
    int D  = t * 4;
    int hh = t >> 5;
    int dd = D & 127;
    int bh2 = b * 8 + hh;

    const float* pp = g_partial + bh2 * (NT * DV) + dd;
    float4 a = make_float4(0.f, 0.f, 0.f, 0.f);
    #pragma unroll
    for (int k = 0; k < NT; k++) {
        float4 x = __ldcg((const float4*)(pp + k * DV));
        a.x += x.x; a.y += x.y; a.z += x.z; a.w += x.w;
    }
    float invS = sh_invS[hh];
    a.x *= invS; a.y *= invS; a.z *= invS; a.w *= invS;

    float s = a.x + a.y + a.z + a.w;
    float q = a.x * a.x + a.y * a.y + a.z * a.z + a.w * a.w;
    #pragma unroll
    for (int o = 16; o > 0; o >>= 1) {
        s += __shfl_xor_sync(0xffffffffu, s, o);
        q += __shfl_xor_sync(0xffffffffu, q, o);
    }
    if (lane == 0) { sh_s[w] = s; sh_q[w] = q; }
    __syncthreads();
    if (w == 0 && lane < 8) {
        s = sh_s[lane];
        q = sh_q[lane];
        #pragma unroll
        for (int o = 4; o > 0; o >>= 1) {
            s += __shfl_xor_sync(0x000000ffu, s, o);
            q += __shfl_xor_sync(0x000000ffu, q, o);
        }
        if (lane == 0) { sh_s[0] = s; sh_q[0] = q; }
    }
    __syncthreads();
    float mean = sh_s[0] * (1.0f / EDv);
    float var  = sh_q[0] * (1.0f / EDv) - mean * mean;
    float inv  = rsqrtf(var + 1e-5f);

    float4 gm = *(const float4*)(gamma + D);
    float4 bt = *(const float4*)(beta + D);
    float4 o4;
    o4.x = (a.x - mean) * inv * gm.x + bt.x;
    o4.y = (a.y - mean) * inv * gm.y + bt.y;
    o4.z = (a.z - mean) * inv * gm.z + bt.z;
    o4.w = (a.w - mean) * inv * gm.w + bt.w;
    *(float4*)(out + b * EDv + D) = o4;

    if (t == 0) g_cnt[b] = 0;       // reset for next graph replay
}

// ---------------------------------------------------------------------------
// Launch
// ---------------------------------------------------------------------------
extern "C" void kernel_launch(void* const* d_in, const int* in_sizes, int n_in,
                              void* d_out, int out_size) {
    const float* keys   = (const float*)d_in[0];
    const float* values = (const float*)d_in[1];
    const float* query  = (const float*)d_in[2];
    const float* k_bias = (const float*)d_in[3];
    const float* v_bias = (const float*)d_in[4];
    const float* sw     = (const float*)d_in[5];
    const float* sb     = (const float*)d_in[6];
    const float* gamma  = (const float*)d_in[7];
    const float* beta   = (const float*)d_in[8];
    float* out = (float*)d_out;

    dim3 g1(NT, BH);
    k_fused<<<g1, 256>>>(keys, k_bias, values, v_bias, query, sw, sb,
                         gamma, beta, out);
}